// round 2
// baseline (speedup 1.0000x reference)
#include <cuda_runtime.h>
#include <cuda_bf16.h>
#include <math.h>

// ---------------------------------------------------------------------------
// Problem constants
// ---------------------------------------------------------------------------
#define BB     8          // batch
#define SS     2048       // seq len
#define TT     (BB*SS)    // tokens = 16384
#define DM     256        // d_model
#define DI     512        // d_inner
#define DSTATE 16
#define DCONV  4
#define NVOCAB 256
#define LOG_VOCAB_F 5.5451774444795623f
#define RMS_EPS 1.1920928955078125e-7f

// ---------------------------------------------------------------------------
// Scratch (device globals: allocation-free per harness rules)
// ---------------------------------------------------------------------------
__device__ float g_x    [TT * DM];        // activations (residual stream)
__device__ float g_xinz [TT * 2 * DI];    // in_proj output (x_in | z)
__device__ float g_xc   [TT * DI];        // conv+silu output
__device__ float g_dt   [TT * DI];        // dt pre-activation
__device__ float g_Bm   [TT * DSTATE];    // B matrix (x_proj first half)
__device__ float g_u    [TT * DI];        // gated y before out_proj
__device__ float g_y2   [TT * DM];        // out_proj output
__device__ float g_log  [TT * NVOCAB];    // head logits
__device__ float g_ent  [TT];             // normalized entropy
__device__ int   g_pstart[BB * SS];       // patch start index per (b,p)
__device__ int   g_np    [BB];            // num patches per batch row

// ---------------------------------------------------------------------------
// Embedding lookup
// ---------------------------------------------------------------------------
__global__ void embed_kernel(const int* __restrict__ bytes,
                             const float* __restrict__ embW,
                             float* __restrict__ x) {
    int idx = blockIdx.x * blockDim.x + threadIdx.x;   // over TT*DM
    int t = idx >> 8;          // /256
    int d = idx & 255;
    x[idx] = embW[bytes[t] * DM + d];
}

// ---------------------------------------------------------------------------
// Tiled fp32 GEMM:  C[M,N] = A[M,K] @ W[K,N]   (all row-major, strides given)
// blockDim = 256 threads, each computes TM x TN outputs.
// ---------------------------------------------------------------------------
template<int BM, int BN, int BK, int TM, int TN>
__global__ void gemm_kernel(const float* __restrict__ A, int lda,
                            const float* __restrict__ W, int ldw,
                            float* __restrict__ C, int ldc,
                            int K) {
    __shared__ float As[BK][BM + 4];
    __shared__ float Ws[BK][BN];

    const int tid = threadIdx.x;
    const int nTx = BN / TN;
    const int tx  = tid % nTx;
    const int ty  = tid / nTx;
    const int rowBase = blockIdx.y * BM;
    const int colBase = blockIdx.x * BN;

    float acc[TM][TN];
    #pragma unroll
    for (int i = 0; i < TM; i++)
        #pragma unroll
        for (int j = 0; j < TN; j++) acc[i][j] = 0.f;

    for (int k0 = 0; k0 < K; k0 += BK) {
        #pragma unroll
        for (int i = tid; i < BM * BK; i += 256) {
            int m  = i / BK;
            int kk = i % BK;
            As[kk][m] = A[(size_t)(rowBase + m) * lda + k0 + kk];
        }
        #pragma unroll
        for (int i = tid; i < BK * BN; i += 256) {
            int kk = i / BN;
            int n  = i % BN;
            Ws[kk][n] = W[(size_t)(k0 + kk) * ldw + colBase + n];
        }
        __syncthreads();

        #pragma unroll
        for (int kk = 0; kk < BK; kk++) {
            float a[TM], b[TN];
            #pragma unroll
            for (int i = 0; i < TM; i++) a[i] = As[kk][ty * TM + i];
            #pragma unroll
            for (int j = 0; j < TN; j++) b[j] = Ws[kk][tx * TN + j];
            #pragma unroll
            for (int i = 0; i < TM; i++)
                #pragma unroll
                for (int j = 0; j < TN; j++)
                    acc[i][j] = fmaf(a[i], b[j], acc[i][j]);
        }
        __syncthreads();
    }

    #pragma unroll
    for (int i = 0; i < TM; i++)
        #pragma unroll
        for (int j = 0; j < TN; j++)
            C[(size_t)(rowBase + ty * TM + i) * ldc + colBase + tx * TN + j] = acc[i][j];
}

// ---------------------------------------------------------------------------
// Causal depthwise conv (width 4) + bias + silu.  x_in = first DI cols of xinz.
// ---------------------------------------------------------------------------
__global__ void conv_silu_kernel(const float* __restrict__ xinz,
                                 const float* __restrict__ cw,   // [DI, DCONV]
                                 const float* __restrict__ cb,   // [DI]
                                 float* __restrict__ xc) {
    int idx = blockIdx.x * blockDim.x + threadIdx.x;   // over TT*DI
    int t = idx / DI;
    int d = idx - t * DI;
    int b = t / SS;
    int s = t - b * SS;

    float acc = cb[d];
    #pragma unroll
    for (int k = 0; k < DCONV; k++) {
        int ss = s - (DCONV - 1) + k;
        if (ss >= 0)
            acc = fmaf(cw[d * DCONV + k],
                       xinz[(size_t)(b * SS + ss) * (2 * DI) + d], acc);
    }
    // silu
    xc[idx] = acc / (1.f + expf(-acc));
}

// ---------------------------------------------------------------------------
// Fused Mamba pointwise core:
//   dt = softplus(dtpre + dtb)
//   y  = dt*xc*sum_n exp(-exp(A_log[d,n])*dt)*B[n] + D*xc
//   u  = y * silu(z)
// negA stored TRANSPOSED in smem: [n][d] -> conflict-free lane reads.
// ---------------------------------------------------------------------------
#define EW_TOKS 8
__global__ void mamba_ew_kernel(const float* __restrict__ dtpre,
                                const float* __restrict__ xc,
                                const float* __restrict__ xinz,
                                const float* __restrict__ Bmat,
                                const float* __restrict__ Alog,  // [DI, DSTATE]
                                const float* __restrict__ dtb,   // [DI]
                                const float* __restrict__ Dp,    // [DI]
                                float* __restrict__ u) {
    __shared__ float negAT[DSTATE][DI];   // 32 KB
    __shared__ float sdtb[DI];
    __shared__ float sD[DI];
    __shared__ float sB[DSTATE];

    const int tid = threadIdx.x;
    for (int i = tid; i < DI * DSTATE; i += 256) {
        int d = i / DSTATE, n = i % DSTATE;
        negAT[n][d] = -expf(Alog[i]);
    }
    for (int i = tid; i < DI; i += 256) { sdtb[i] = dtb[i]; sD[i] = Dp[i]; }
    __syncthreads();

    for (int tok = 0; tok < EW_TOKS; tok++) {
        int t = blockIdx.x * EW_TOKS + tok;
        if (tid < DSTATE) sB[tid] = Bmat[t * DSTATE + tid];
        __syncthreads();

        #pragma unroll
        for (int rep = 0; rep < 2; rep++) {
            int d = tid + rep * 256;
            float v   = dtpre[(size_t)t * DI + d] + sdtb[d];
            // stable softplus = max(v,0) + log1p(exp(-|v|))
            float dtv = fmaxf(v, 0.f) + log1pf(expf(-fabsf(v)));
            float xcv = xc[(size_t)t * DI + d];
            float accn = 0.f;
            #pragma unroll
            for (int n = 0; n < DSTATE; n++)
                accn = fmaf(expf(negAT[n][d] * dtv), sB[n], accn);
            float yv = dtv * xcv * accn + sD[d] * xcv;
            float zv = xinz[(size_t)t * (2 * DI) + DI + d];
            u[(size_t)t * DI + d] = yv * (zv / (1.f + expf(-zv)));
        }
        __syncthreads();
    }
}

// ---------------------------------------------------------------------------
// Residual add + RMSNorm (in-place into x). 1 block per token, 256 threads.
// ---------------------------------------------------------------------------
__global__ void rmsnorm_add_kernel(float* __restrict__ x,
                                   const float* __restrict__ y2,
                                   const float* __restrict__ nw) {
    __shared__ float red[256];
    int t = blockIdx.x;
    int d = threadIdx.x;
    float v = y2[(size_t)t * DM + d] + x[(size_t)t * DM + d];
    red[d] = v * v;
    __syncthreads();
    for (int s = 128; s > 0; s >>= 1) {
        if (d < s) red[d] += red[d + s];
        __syncthreads();
    }
    float scale = rsqrtf(red[0] * (1.f / DM) + RMS_EPS);
    x[(size_t)t * DM + d] = v * scale * nw[d];
}

// ---------------------------------------------------------------------------
// Entropy of softmax(logits) per token, normalized by log(VOCAB).
// ---------------------------------------------------------------------------
__global__ void entropy_kernel(const float* __restrict__ logits,
                               float* __restrict__ ent) {
    __shared__ float red[256];
    int t = blockIdx.x;
    int d = threadIdx.x;
    float l = logits[(size_t)t * NVOCAB + d];

    red[d] = l;
    __syncthreads();
    for (int s = 128; s > 0; s >>= 1) {
        if (d < s) red[d] = fmaxf(red[d], red[d + s]);
        __syncthreads();
    }
    float m = red[0];
    __syncthreads();

    float e = expf(l - m);
    red[d] = e;
    __syncthreads();
    for (int s = 128; s > 0; s >>= 1) {
        if (d < s) red[d] += red[d + s];
        __syncthreads();
    }
    float Z = red[0];
    __syncthreads();

    red[d] = e * l;
    __syncthreads();
    for (int s = 128; s > 0; s >>= 1) {
        if (d < s) red[d] += red[d + s];
        __syncthreads();
    }
    float sumel = red[0];

    if (d == 0) {
        float lse = m + logf(Z);
        float H = lse - sumel / Z;
        ent[t] = H / LOG_VOCAB_F;
    }
}

// ---------------------------------------------------------------------------
// Sequential boundary automaton per batch row. Also emits byte_to_patch (as
// float, straight into the output buffer) and patch_start/num_patches.
// ---------------------------------------------------------------------------
__global__ void boundary_kernel(const float* __restrict__ ent,
                                int* __restrict__ pstart,
                                int* __restrict__ np,
                                float* __restrict__ out_b2p) {
    __shared__ float se[SS];
    int b = blockIdx.x;
    for (int i = threadIdx.x; i < SS; i += blockDim.x)
        se[i] = ent[b * SS + i];
    __syncthreads();

    if (threadIdx.x == 0) {
        int size = 1;
        int p = 0;
        pstart[b * SS + 0] = 0;
        out_b2p[b * SS + 0] = 0.f;
        for (int s = 1; s < SS; s++) {
            float e = se[s];
            bool nb = (e > 0.5f) || (size >= 8);   // MIN_P=1 always satisfied
            if (nb) { p++; pstart[b * SS + p] = s; size = 1; }
            else    { size++; }
            out_b2p[b * SS + s] = (float)p;
        }
        np[b] = p + 1;
    }
}

// ---------------------------------------------------------------------------
// Patch mean pooling: 1 block per (b, p); patches are contiguous byte ranges.
// ---------------------------------------------------------------------------
__global__ void pool_kernel(const float* __restrict__ be,
                            const int* __restrict__ pstart,
                            const int* __restrict__ np,
                            float* __restrict__ out_emb,
                            float* __restrict__ out_len) {
    int blk = blockIdx.x;
    int b = blk / SS;
    int p = blk - b * SS;
    int d = threadIdx.x;
    int npb = np[b];

    if (p < npb) {
        int s0 = pstart[b * SS + p];
        int s1 = (p + 1 < npb) ? pstart[b * SS + p + 1] : SS;
        float sum = 0.f;
        for (int s = s0; s < s1; s++)
            sum += be[(size_t)(b * SS + s) * DM + d];
        out_emb[(size_t)blk * DM + d] = sum / (float)(s1 - s0);
        if (d == 0) out_len[blk] = (float)(s1 - s0);
    } else {
        out_emb[(size_t)blk * DM + d] = 0.f;
        if (d == 0) out_len[blk] = 0.f;
    }
}

// ---------------------------------------------------------------------------
// Launch
// ---------------------------------------------------------------------------
extern "C" void kernel_launch(void* const* d_in, const int* in_sizes, int n_in,
                              void* d_out, int out_size) {
    const int*   bytes = (const int*)  d_in[0];
    const float* be    = (const float*)d_in[1];
    const float* embW  = (const float*)d_in[2];
    const float* inW   = (const float*)d_in[3];
    const float* cw    = (const float*)d_in[4];
    const float* cb    = (const float*)d_in[5];
    const float* xpW   = (const float*)d_in[6];
    const float* dtW   = (const float*)d_in[7];
    const float* dtb   = (const float*)d_in[8];
    const float* Alog  = (const float*)d_in[9];
    const float* Dp    = (const float*)d_in[10];
    const float* outW  = (const float*)d_in[11];
    const float* nw    = (const float*)d_in[12];
    const float* headW = (const float*)d_in[13];
    float* out = (float*)d_out;

    static float *px=nullptr, *pxinz, *pxc, *pdt, *pB, *pu, *py2, *plog, *pent;
    static int *ppstart, *pnp;
    if (!px) {
        cudaGetSymbolAddress((void**)&px,     g_x);
        cudaGetSymbolAddress((void**)&pxinz,  g_xinz);
        cudaGetSymbolAddress((void**)&pxc,    g_xc);
        cudaGetSymbolAddress((void**)&pdt,    g_dt);
        cudaGetSymbolAddress((void**)&pB,     g_Bm);
        cudaGetSymbolAddress((void**)&pu,     g_u);
        cudaGetSymbolAddress((void**)&py2,    g_y2);
        cudaGetSymbolAddress((void**)&plog,   g_log);
        cudaGetSymbolAddress((void**)&pent,   g_ent);
        cudaGetSymbolAddress((void**)&ppstart,g_pstart);
        cudaGetSymbolAddress((void**)&pnp,    g_np);
    }

    // 1) embedding
    embed_kernel<<<TT * DM / 256, 256>>>(bytes, embW, px);

    // 2) two mamba blocks
    for (int l = 0; l < 2; l++) {
        // x @ in_proj  -> xinz  (M=TT, N=1024, K=256)
        gemm_kernel<128,64,16,8,4><<<dim3(1024/64, TT/128), 256>>>(
            px, DM, inW + (size_t)l * DM * 2 * DI, 2 * DI, pxinz, 2 * DI, DM);
        // depthwise conv + silu
        conv_silu_kernel<<<TT * DI / 256, 256>>>(
            pxinz, cw + (size_t)l * DI * DCONV, cb + (size_t)l * DI, pxc);
        // xc @ dt_w -> dtpre  (N=512, K=512)
        gemm_kernel<128,64,16,8,4><<<dim3(512/64, TT/128), 256>>>(
            pxc, DI, dtW + (size_t)l * DI * DI, DI, pdt, DI, DI);
        // xc @ x_proj[:, :16] -> Bmat  (N=16, K=512, ldw=32)
        gemm_kernel<64,16,32,4,1><<<dim3(1, TT/64), 256>>>(
            pxc, DI, xpW + (size_t)l * DI * 2 * DSTATE, 2 * DSTATE, pB, DSTATE, DI);
        // fused pointwise core -> u
        mamba_ew_kernel<<<TT / EW_TOKS, 256>>>(
            pdt, pxc, pxinz, pB,
            Alog + (size_t)l * DI * DSTATE, dtb + (size_t)l * DI,
            Dp + (size_t)l * DI, pu);
        // u @ out_w -> y2  (N=256, K=512)
        gemm_kernel<128,64,16,8,4><<<dim3(256/64, TT/128), 256>>>(
            pu, DI, outW + (size_t)l * DI * DM, DM, py2, DM, DI);
        // residual + rmsnorm (in-place x)
        rmsnorm_add_kernel<<<TT, 256>>>(px, py2, nw + (size_t)l * DM);
    }

    // 3) head + entropy
    gemm_kernel<128,64,16,8,4><<<dim3(NVOCAB/64, TT/128), 256>>>(
        px, DM, headW, NVOCAB, plog, NVOCAB, DM);
    entropy_kernel<<<TT, 256>>>(plog, pent);

    // 4) boundaries (writes byte_to_patch floats straight into d_out tail)
    boundary_kernel<<<BB, 256>>>(pent, ppstart, pnp, out + (size_t)TT * DM + TT);

    // 5) patch pooling (patch_embeddings + patch_lengths)
    pool_kernel<<<BB * SS, 256>>>(be, ppstart, pnp, out, out + (size_t)TT * DM);
}